// round 15
// baseline (speedup 1.0000x reference)
#include <cuda_runtime.h>
#include <cuda_fp16.h>
#include <math_constants.h>
#include <cstdint>

// ---------------------------------------------------------------------------
// Problem constants
// ---------------------------------------------------------------------------
#define N_ROWS 32768
#define DDIM   128
#define KCODE  1024
#define NDTOT  (N_ROWS * DDIM)   // 4194304
#define KEXT   144               // 128 dims + 1 esq-fold dim + 15 zero pad
#define QMARG  0.024f            // acc units = d2 9.4e-5

// scratch (no cudaMalloc allowed)
__device__ __align__(16) __half g_x_hi[NDTOT];
__device__ __align__(16) __half g_e_ext[KCODE * KEXT];
__device__ float        g_xsq[N_ROWS];
__device__ float        g_esq[KCODE];
__device__ int          g_idx[N_ROWS];
__device__ int          g_refrows[N_ROWS];
__device__ unsigned int g_nref;
__device__ double       g_part[1024];
__device__ unsigned int g_done;

// ---------------------------------------------------------------------------
// helpers
// ---------------------------------------------------------------------------
__device__ __forceinline__ uint32_t smem_to_u32(const void* p) {
    uint32_t a;
    asm("{ .reg .u64 t; cvta.to.shared.u64 t, %1; cvt.u32.u64 %0, t; }"
        : "=r"(a) : "l"(p));
    return a;
}

__device__ __forceinline__ void ldsm4(uint32_t* r, uint32_t addr) {
    asm volatile("ldmatrix.sync.aligned.m8n8.x4.shared.b16 {%0,%1,%2,%3}, [%4];"
                 : "=r"(r[0]), "=r"(r[1]), "=r"(r[2]), "=r"(r[3]) : "r"(addr));
}

__device__ __forceinline__ void mma16816(float* d, const uint32_t* a,
                                         const uint32_t* b) {
    asm volatile(
        "mma.sync.aligned.m16n8k16.row.col.f32.f16.f16.f32 "
        "{%0,%1,%2,%3}, {%4,%5,%6,%7}, {%8,%9}, {%0,%1,%2,%3};"
        : "+f"(d[0]), "+f"(d[1]), "+f"(d[2]), "+f"(d[3])
        : "r"(a[0]), "r"(a[1]), "r"(a[2]), "r"(a[3]), "r"(b[0]), "r"(b[1]));
}

// packed fp32x2 FMA (R3-proven exact-dot building block)
__device__ __forceinline__ void fma2(unsigned long long& d,
                                     unsigned long long a,
                                     unsigned long long b) {
    asm("fma.rn.f32x2 %0, %1, %2, %0;" : "+l"(d) : "l"(a), "l"(b));
}

__device__ __forceinline__ void cpasync16(uint32_t dst, const void* src) {
    asm volatile("cp.async.cg.shared.global [%0], [%1], 16;"
                 :: "r"(dst), "l"(src) : "memory");
}

// cp.async a [rows x rowlen-half] tile into padded smem
__device__ __forceinline__ void load_tile(uint32_t dst,
                                          const __half* __restrict__ g,
                                          int rows, int chunks, int strb,
                                          int rowlen, int t, int nt) {
    for (int c = t; c < rows * chunks; c += nt) {
        int r = c / chunks, ch = c - r * chunks;
        cpasync16(dst + (uint32_t)r * strb + ch * 16,
                  (const void*)(g + (size_t)r * rowlen + ch * 8));
    }
}

// pass-1 smem layout (bytes)
#define STRB_A  272
#define STRB_B  304
#define SA_HI   0
#define SB      34816
#define SB_STAGE 19456
#define SMEM_P1 73728   // x2 CTAs = 147456 <= 227KB/SM

// refine smem layout (bytes)
#define RXS     0               // 16 x 132 floats = 8448
#define RES     8448            // 2 stages x 64 x 132 floats (stage 33792)
#define RES_STG 33792
#define RESQ    76032           // 1024 floats
#define RCV     80128           // 16x16 floats
#define RCK     81152           // 16x16 ints
#define SMEM_RF 82176

// ---------------------------------------------------------------------------
// e_sq + g_nref reset
// ---------------------------------------------------------------------------
__global__ void esq_kernel(const float* __restrict__ emb) {
    if (blockIdx.x == 0 && threadIdx.x == 0) g_nref = 0;
    int warp = (blockIdx.x * blockDim.x + threadIdx.x) >> 5;
    int lane = threadIdx.x & 31;
    if (warp < KCODE) {
        float4 v = *(const float4*)&emb[(size_t)warp * DDIM + lane * 4];
        float s = v.x * v.x + v.y * v.y + v.z * v.z + v.w * v.w;
        #pragma unroll
        for (int o = 16; o > 0; o >>= 1)
            s += __shfl_xor_sync(0xffffffffu, s, o);
        if (lane == 0) g_esq[warp] = s;
    }
}

// emb -> extended fp16: cols 0..127 = e*512, col 128 = -256*esq, 129..143 = 0
__global__ void convert_emb_kernel(const float* __restrict__ emb) {
    int i = blockIdx.x * blockDim.x + threadIdx.x;
    if (i < KCODE * KEXT) {
        int k = i / KEXT, col = i - k * KEXT;
        float v = 0.0f;
        if (col < DDIM)       v = emb[k * DDIM + col] * 512.0f;
        else if (col == DDIM) v = -256.0f * g_esq[k];
        g_e_ext[i] = __float2half_rn(v);
    }
}

// x -> fp16 + per-row x_sq (serial ascending-d, matches R3)
__global__ __launch_bounds__(256)
void convert_x_kernel(const float* __restrict__ x) {
    __shared__ float xs[64 * 132];
    const int rb = blockIdx.x * 64;
    const float4* xg = (const float4*)(x + (size_t)rb * DDIM);
    for (int t = threadIdx.x; t < 64 * 32; t += 256) {
        int r = t >> 5, c = t & 31;
        *(float4*)&xs[r * 132 + c * 4] = xg[r * 32 + c];
    }
    __syncthreads();
    if (threadIdx.x < 64) {
        const float* row = &xs[threadIdx.x * 132];
        float s = 0.0f;
        #pragma unroll 8
        for (int d = 0; d < DDIM; ++d)
            s = __fadd_rn(s, __fmul_rn(row[d], row[d]));
        g_xsq[rb + threadIdx.x] = s;
    }
    for (int i = threadIdx.x; i < 64 * DDIM; i += 256) {
        int r = i >> 7, c = i & 127;
        g_x_hi[(size_t)(rb + r) * DDIM + c] = __float2half_rn(xs[r * 132 + c]);
    }
}

// ---------------------------------------------------------------------------
// Pass 1: hi-only HMMA, esq folded into K-dim -> argmax(acc) == argmin(d2).
// Per-thread top-2 (4-op branchless) + two-phase quad merge (argmax butterfly,
// then v2 = max over lanes of winner?m2:m1). Rows with gap < QMARG queued.
// ---------------------------------------------------------------------------
__global__ __launch_bounds__(128, 2)
void vq_pass1(float* __restrict__ out)
{
    extern __shared__ __align__(16) char smem[];
    const uint32_t sb = smem_to_u32(smem);
    const int tid  = threadIdx.x;
    const int lane = tid & 31;
    const int wm   = tid >> 5;
    const int gID  = lane >> 2;
    const int tig  = lane & 3;
    const int rbase = blockIdx.x * 128;

    // prologue: group0 = A; group1 = B stage0; group2 = B stage1
    load_tile(sb + SA_HI, g_x_hi + (size_t)rbase * DDIM, 128, 16, STRB_A, DDIM, tid, 128);
    asm volatile("cp.async.commit_group;" ::: "memory");
    load_tile(sb + SB,            g_e_ext,             64, 18, STRB_B, KEXT, tid, 128);
    asm volatile("cp.async.commit_group;" ::: "memory");
    load_tile(sb + SB + SB_STAGE, g_e_ext + 64 * KEXT, 64, 18, STRB_B, KEXT, tid, 128);
    asm volatile("cp.async.commit_group;" ::: "memory");

    float m1[2][2], m2[2][2];
    int   k1[2][2];
    #pragma unroll
    for (int mf = 0; mf < 2; ++mf)
        #pragma unroll
        for (int h = 0; h < 2; ++h) {
            m1[mf][h] = -CUDART_INF_F; m2[mf][h] = -CUDART_INF_F; k1[mf][h] = 0;
        }

    const uint32_t a_off = (uint32_t)((wm * 32 + (lane & 15)) * STRB_A + (lane >> 4) * 16);
    const uint32_t b_off = (uint32_t)(((lane & 7) + ((lane >> 4) << 3)) * STRB_B
                                      + ((lane >> 3) & 1) * 16);

    // constant A fragment for the ext k-step: x_ext = [1, 0, ..., 0]
    uint32_t aext[4];
    aext[0] = aext[1] = (tig == 0) ? 0x00003C00u : 0u;
    aext[2] = aext[3] = 0u;

    asm volatile("cp.async.wait_group 2;" ::: "memory");
    __syncthreads();
    uint32_t aHr[8][2][4];
    #pragma unroll
    for (int ks = 0; ks < 8; ++ks)
        #pragma unroll
        for (int mf = 0; mf < 2; ++mf)
            ldsm4(aHr[ks][mf], sb + SA_HI + a_off + mf * 4352 + ks * 32);

    for (int it = 0; it < 16; ++it) {
        asm volatile("cp.async.wait_group 1;" ::: "memory");
        __syncthreads();
        const uint32_t bs = sb + SB + (uint32_t)(it & 1) * SB_STAGE;

        float acc[2][8][4];
        #pragma unroll
        for (int mf = 0; mf < 2; ++mf)
            #pragma unroll
            for (int nf = 0; nf < 8; ++nf)
                #pragma unroll
                for (int r = 0; r < 4; ++r) acc[mf][nf][r] = 0.0f;

        uint32_t bHb[2][4][4];
        #pragma unroll
        for (int p = 0; p < 4; ++p)
            ldsm4(bHb[0][p], bs + b_off + p * 4864);

        #pragma unroll
        for (int ks = 0; ks < 9; ++ks) {
            const int cur = ks & 1, nxt = cur ^ 1;
            if (ks < 8) {
                #pragma unroll
                for (int p = 0; p < 4; ++p)
                    ldsm4(bHb[nxt][p], bs + b_off + p * 4864 + (ks + 1) * 32);
            }
            #pragma unroll
            for (int mf = 0; mf < 2; ++mf) {
                const uint32_t* A = (ks < 8) ? aHr[ks][mf] : aext;
                #pragma unroll
                for (int p = 0; p < 4; ++p) {
                    mma16816(acc[mf][2 * p],     A, &bHb[cur][p][0]);
                    mma16816(acc[mf][2 * p + 1], A, &bHb[cur][p][2]);
                }
            }
        }

        // epilogue: branchless top-2 max of raw acc; k ascending per thread
        #pragma unroll
        for (int mf = 0; mf < 2; ++mf)
            #pragma unroll
            for (int nf = 0; nf < 8; ++nf) {
                const int kb = it * 64 + nf * 8 + 2 * tig;
                const float* a4 = acc[mf][nf];
                #pragma unroll
                for (int h = 0; h < 2; ++h)
                    #pragma unroll
                    for (int j = 0; j < 2; ++j) {
                        float v = a4[h * 2 + j];
                        bool gt = v > m1[mf][h];
                        m2[mf][h] = gt ? m1[mf][h] : fmaxf(m2[mf][h], v);
                        k1[mf][h] = gt ? (kb + j) : k1[mf][h];
                        m1[mf][h] = gt ? v : m1[mf][h];
                    }
            }

        __syncthreads();
        if (it + 2 < 16)
            load_tile(bs, g_e_ext + (size_t)(it + 2) * 64 * KEXT, 64, 18, STRB_B, KEXT, tid, 128);
        asm volatile("cp.async.commit_group;" ::: "memory");
    }

    // two-phase quad merge
    #pragma unroll
    for (int mf = 0; mf < 2; ++mf)
        #pragma unroll
        for (int h = 0; h < 2; ++h) {
            // phase 1: global argmax (first-k on acc ties)
            float v1 = m1[mf][h];
            int   kk = k1[mf][h];
            #pragma unroll
            for (int o = 1; o <= 2; o <<= 1) {
                float ov = __shfl_xor_sync(0xffffffffu, v1, o);
                int   ok = __shfl_xor_sync(0xffffffffu, kk, o);
                if (ov > v1 || (ov == v1 && ok < kk)) { v1 = ov; kk = ok; }
            }
            // phase 2: v2 = max over lanes of (lane holds winner ? m2 : m1)
            float cand = (k1[mf][h] == kk) ? m2[mf][h] : m1[mf][h];
            #pragma unroll
            for (int o = 1; o <= 2; o <<= 1)
                cand = fmaxf(cand, __shfl_xor_sync(0xffffffffu, cand, o));

            if (tig == 0) {
                int row = rbase + wm * 32 + mf * 16 + gID + h * 8;
                g_idx[row] = kk;
                out[NDTOT + 1 + row] = (float)kk;
                if (v1 - cand < QMARG) {
                    unsigned q = atomicAdd(&g_nref, 1u);
                    g_refrows[q] = row;
                }
            }
        }
}

// ---------------------------------------------------------------------------
// Pass 2 refine: exact f32x2 distance (R3 pairing & rounding) for queued rows
// over ALL 1024 codes. 16 rows/group share emb chunks, double-buffered via
// cp.async so staging overlaps compute. First-min tie-break preserved.
// ---------------------------------------------------------------------------
__global__ __launch_bounds__(256)
void vq_refine(const float* __restrict__ x,
               const float* __restrict__ emb,
               float* __restrict__ out)
{
    extern __shared__ __align__(16) char smem[];
    const uint32_t sb = smem_to_u32(smem);
    float* xs    = (float*)(smem + RXS);     // [16][132]
    float* esq_s = (float*)(smem + RESQ);
    float* candv = (float*)(smem + RCV);
    int*   candk = (int*)(smem + RCK);
    const int t = threadIdx.x;
    const int row16 = t >> 4;
    const int col16 = t & 15;
    const int n = (int)g_nref;

    for (int i = t; i < KCODE; i += 256) esq_s[i] = g_esq[i];

    for (int g = blockIdx.x; g * 16 < n; g += gridDim.x) {
        __syncthreads();   // smem reuse guard across groups
        // gather 16 x-rows (tail clamped to last valid entry; benign dupes)
        for (int c = t; c < 16 * 32; c += 256) {
            int r = c >> 5, cc = c & 31;
            int e = g * 16 + r;
            int rid = g_refrows[e < n ? e : n - 1];
            *(float4*)&xs[r * 132 + cc * 4] =
                ((const float4*)(x + (size_t)rid * DDIM))[cc];
        }
        // prologue: stage chunk 0 and 1
        #pragma unroll
        for (int s = 0; s < 2; ++s) {
            for (int c = t; c < 64 * 32; c += 256) {
                int r = c >> 5, cc = c & 31;
                cpasync16(sb + RES + s * RES_STG + (uint32_t)r * 528 + cc * 16,
                          (const void*)(emb + (size_t)(s * 64 + r) * DDIM + cc * 4));
            }
            asm volatile("cp.async.commit_group;" ::: "memory");
        }

        const int myrow = g * 16 + row16;
        const float xsq = g_xsq[g_refrows[myrow < n ? myrow : n - 1]];

        float bv = CUDART_INF_F;
        int   bk = 0x7fffffff;
        for (int ch = 0; ch < 16; ++ch) {
            asm volatile("cp.async.wait_group 1;" ::: "memory");
            __syncthreads();
            const char* es = smem + RES + (ch & 1) * RES_STG;
            const ulonglong2* xr = (const ulonglong2*)(xs + row16 * 132);
            #pragma unroll
            for (int jj = 0; jj < 4; ++jj) {
                const int kl = col16 + jj * 16;
                const int k  = ch * 64 + kl;
                const ulonglong2* er = (const ulonglong2*)(es + kl * 528);
                unsigned long long acc = 0ULL;
                #pragma unroll 4
                for (int c = 0; c < 32; ++c) {
                    ulonglong2 xv = xr[c];
                    ulonglong2 ev = er[c];
                    fma2(acc, xv.x, ev.x);
                    fma2(acc, xv.y, ev.y);
                }
                float2 p = *reinterpret_cast<float2*>(&acc);
                float dot = __fadd_rn(p.x, p.y);
                float d2 = __fadd_rn(__fsub_rn(xsq, 2.0f * dot), esq_s[k]);
                if (d2 < bv) { bv = d2; bk = k; }
            }
            __syncthreads();   // all done reading stage (ch&1)
            if (ch + 2 < 16) {
                for (int c = t; c < 64 * 32; c += 256) {
                    int r = c >> 5, cc = c & 31;
                    cpasync16(sb + RES + (ch & 1) * RES_STG + (uint32_t)r * 528 + cc * 16,
                              (const void*)(emb + (size_t)((ch + 2) * 64 + r) * DDIM + cc * 4));
                }
            }
            asm volatile("cp.async.commit_group;" ::: "memory");
        }
        candv[row16 * 16 + col16] = bv;
        candk[row16 * 16 + col16] = bk;
        __syncthreads();
        if (t < 16) {
            float v = candv[t * 16];
            int   k = candk[t * 16];
            #pragma unroll
            for (int c = 1; c < 16; ++c) {
                float vo = candv[t * 16 + c];
                int   ko = candk[t * 16 + c];
                if (vo < v || (vo == v && ko < k)) { v = vo; k = ko; }
            }
            int e = g * 16 + t;
            if (e < n) {
                int rid = g_refrows[e];
                g_idx[rid] = k;
                out[NDTOT + 1 + rid] = (float)k;
            }
        }
    }
}

// ---------------------------------------------------------------------------
// quantized output (gather) + fp64 MSE, loss finalized by last block
// ---------------------------------------------------------------------------
__global__ __launch_bounds__(256)
void quant_kernel(const float* __restrict__ x,
                  const float* __restrict__ emb,
                  float* __restrict__ out)
{
    __shared__ double sred[256];
    __shared__ bool last;
    const int total4 = NDTOT / 4;  // 1048576
    double s = 0.0;
    for (int p = blockIdx.x * 256 + threadIdx.x; p < total4; p += gridDim.x * 256) {
        int row = p >> 5, d4 = p & 31;
        int k = g_idx[row];
        float4 q  = *(const float4*)&emb[(size_t)k * DDIM + d4 * 4];
        float4 xv = *(const float4*)&x[(size_t)p * 4];
        ((float4*)out)[p] = q;
        float a = q.x - xv.x, b = q.y - xv.y, c = q.z - xv.z, d = q.w - xv.w;
        s += (double)a * a + (double)b * b + (double)c * c + (double)d * d;
    }
    sred[threadIdx.x] = s;
    __syncthreads();
    for (int o = 128; o > 0; o >>= 1) {
        if (threadIdx.x < o) sred[threadIdx.x] += sred[threadIdx.x + o];
        __syncthreads();
    }
    if (threadIdx.x == 0) {
        g_part[blockIdx.x] = sred[0];
        __threadfence();
        unsigned v = atomicAdd(&g_done, 1u);
        last = (v == 1023u);
    }
    __syncthreads();
    if (last) {
        double tsum = 0.0;
        for (int i = threadIdx.x; i < 1024; i += 256) tsum += g_part[i];
        sred[threadIdx.x] = tsum;
        __syncthreads();
        for (int o = 128; o > 0; o >>= 1) {
            if (threadIdx.x < o) sred[threadIdx.x] += sred[threadIdx.x + o];
            __syncthreads();
        }
        if (threadIdx.x == 0) {
            out[NDTOT] = (float)(1.25 * (sred[0] / (double)NDTOT));
            g_done = 0;   // reset for next graph replay
        }
    }
}

// ---------------------------------------------------------------------------
extern "C" void kernel_launch(void* const* d_in, const int* in_sizes, int n_in,
                              void* d_out, int out_size)
{
    const float* x   = (const float*)d_in[0];
    const float* emb = (const float*)d_in[1];
    float* out = (float*)d_out;

    cudaFuncSetAttribute(vq_pass1,
                         cudaFuncAttributeMaxDynamicSharedMemorySize, SMEM_P1);
    cudaFuncSetAttribute(vq_refine,
                         cudaFuncAttributeMaxDynamicSharedMemorySize, SMEM_RF);

    esq_kernel<<<KCODE / 8, 256>>>(emb);                          // resets g_nref
    convert_emb_kernel<<<(KCODE * KEXT + 255) / 256, 256>>>(emb); // needs g_esq
    convert_x_kernel<<<N_ROWS / 64, 256>>>(x);
    vq_pass1<<<N_ROWS / 128, 128, SMEM_P1>>>(out);
    vq_refine<<<512, 256, SMEM_RF>>>(x, emb, out);
    quant_kernel<<<1024, 256>>>(x, emb, out);
}

// round 16
// speedup vs baseline: 1.2504x; 1.2504x over previous
#include <cuda_runtime.h>
#include <cuda_fp16.h>
#include <math_constants.h>
#include <cstdint>

// ---------------------------------------------------------------------------
// Problem constants
// ---------------------------------------------------------------------------
#define N_ROWS 32768
#define DDIM   128
#define KCODE  1024
#define NDTOT  (N_ROWS * DDIM)   // 4194304
#define KEXT   144               // 128 dims + 1 esq-fold dim + 15 zero pad
#define QMARG  0.024f            // acc units = d2 9.4e-5

// scratch (no cudaMalloc allowed)
__device__ __align__(16) __half g_x_hi[NDTOT];
__device__ __align__(16) __half g_e_ext[KCODE * KEXT];
__device__ float        g_xsq[N_ROWS];
__device__ float        g_esq[KCODE];
__device__ int          g_idx[N_ROWS];
__device__ int          g_refrows[N_ROWS];
__device__ unsigned int g_nref;
__device__ double       g_part[1024];
__device__ unsigned int g_done;

// ---------------------------------------------------------------------------
// helpers
// ---------------------------------------------------------------------------
__device__ __forceinline__ uint32_t smem_to_u32(const void* p) {
    uint32_t a;
    asm("{ .reg .u64 t; cvta.to.shared.u64 t, %1; cvt.u32.u64 %0, t; }"
        : "=r"(a) : "l"(p));
    return a;
}

__device__ __forceinline__ void ldsm4(uint32_t* r, uint32_t addr) {
    asm volatile("ldmatrix.sync.aligned.m8n8.x4.shared.b16 {%0,%1,%2,%3}, [%4];"
                 : "=r"(r[0]), "=r"(r[1]), "=r"(r[2]), "=r"(r[3]) : "r"(addr));
}

__device__ __forceinline__ void mma16816(float* d, const uint32_t* a,
                                         const uint32_t* b) {
    asm volatile(
        "mma.sync.aligned.m16n8k16.row.col.f32.f16.f16.f32 "
        "{%0,%1,%2,%3}, {%4,%5,%6,%7}, {%8,%9}, {%0,%1,%2,%3};"
        : "+f"(d[0]), "+f"(d[1]), "+f"(d[2]), "+f"(d[3])
        : "r"(a[0]), "r"(a[1]), "r"(a[2]), "r"(a[3]), "r"(b[0]), "r"(b[1]));
}

// packed fp32x2 FMA (R3-proven exact-dot building block)
__device__ __forceinline__ void fma2(unsigned long long& d,
                                     unsigned long long a,
                                     unsigned long long b) {
    asm("fma.rn.f32x2 %0, %1, %2, %0;" : "+l"(d) : "l"(a), "l"(b));
}

__device__ __forceinline__ void cpasync16(uint32_t dst, const void* src) {
    asm volatile("cp.async.cg.shared.global [%0], [%1], 16;"
                 :: "r"(dst), "l"(src) : "memory");
}

// cp.async a [rows x rowlen-half] tile into padded smem
__device__ __forceinline__ void load_tile(uint32_t dst,
                                          const __half* __restrict__ g,
                                          int rows, int chunks, int strb,
                                          int rowlen, int t, int nt) {
    for (int c = t; c < rows * chunks; c += nt) {
        int r = c / chunks, ch = c - r * chunks;
        cpasync16(dst + (uint32_t)r * strb + ch * 16,
                  (const void*)(g + (size_t)r * rowlen + ch * 8));
    }
}

// pass-1 smem layout (bytes)
#define STRB_A  272
#define STRB_B  304
#define SA_HI   0
#define SB      34816
#define SB_STAGE 19456
#define SMEM_P1 73728   // x2 CTAs = 147456 <= 227KB/SM

// refine smem layout (bytes)
#define RXS     0               // 16 x 132 floats = 8448
#define RES     8448            // 2 stages x 64 x 132 floats (stage 33792)
#define RES_STG 33792
#define RESQ    76032           // 1024 floats
#define RCV     80128           // 16x16 floats
#define RCK     81152           // 16x16 ints
#define SMEM_RF 82176

// ---------------------------------------------------------------------------
// e_sq + g_nref reset
// ---------------------------------------------------------------------------
__global__ void esq_kernel(const float* __restrict__ emb) {
    if (blockIdx.x == 0 && threadIdx.x == 0) g_nref = 0;
    int warp = (blockIdx.x * blockDim.x + threadIdx.x) >> 5;
    int lane = threadIdx.x & 31;
    if (warp < KCODE) {
        float4 v = *(const float4*)&emb[(size_t)warp * DDIM + lane * 4];
        float s = v.x * v.x + v.y * v.y + v.z * v.z + v.w * v.w;
        #pragma unroll
        for (int o = 16; o > 0; o >>= 1)
            s += __shfl_xor_sync(0xffffffffu, s, o);
        if (lane == 0) g_esq[warp] = s;
    }
}

// emb -> extended fp16: cols 0..127 = e*512, col 128 = -256*esq, 129..143 = 0
__global__ void convert_emb_kernel(const float* __restrict__ emb) {
    int i = blockIdx.x * blockDim.x + threadIdx.x;
    if (i < KCODE * KEXT) {
        int k = i / KEXT, col = i - k * KEXT;
        float v = 0.0f;
        if (col < DDIM)       v = emb[k * DDIM + col] * 512.0f;
        else if (col == DDIM) v = -256.0f * g_esq[k];
        g_e_ext[i] = __float2half_rn(v);
    }
}

// x -> fp16 + per-row x_sq (serial ascending-d, matches R3)
__global__ __launch_bounds__(256)
void convert_x_kernel(const float* __restrict__ x) {
    __shared__ float xs[64 * 132];
    const int rb = blockIdx.x * 64;
    const float4* xg = (const float4*)(x + (size_t)rb * DDIM);
    for (int t = threadIdx.x; t < 64 * 32; t += 256) {
        int r = t >> 5, c = t & 31;
        *(float4*)&xs[r * 132 + c * 4] = xg[r * 32 + c];
    }
    __syncthreads();
    if (threadIdx.x < 64) {
        const float* row = &xs[threadIdx.x * 132];
        float s = 0.0f;
        #pragma unroll 8
        for (int d = 0; d < DDIM; ++d)
            s = __fadd_rn(s, __fmul_rn(row[d], row[d]));
        g_xsq[rb + threadIdx.x] = s;
    }
    for (int i = threadIdx.x; i < 64 * DDIM; i += 256) {
        int r = i >> 7, c = i & 127;
        g_x_hi[(size_t)(rb + r) * DDIM + c] = __float2half_rn(xs[r * 132 + c]);
    }
}

// ---------------------------------------------------------------------------
// Pass 1: hi-only HMMA, esq folded into K-dim -> argmax(acc) == argmin(d2).
// Per-thread top-2 (branchless) + two-phase quad merge. Rows with
// gap < QMARG queued for exact refine.
// ---------------------------------------------------------------------------
__global__ __launch_bounds__(128, 2)
void vq_pass1(float* __restrict__ out)
{
    extern __shared__ __align__(16) char smem[];
    const uint32_t sb = smem_to_u32(smem);
    const int tid  = threadIdx.x;
    const int lane = tid & 31;
    const int wm   = tid >> 5;
    const int gID  = lane >> 2;
    const int tig  = lane & 3;
    const int rbase = blockIdx.x * 128;

    // prologue: group0 = A; group1 = B stage0; group2 = B stage1
    load_tile(sb + SA_HI, g_x_hi + (size_t)rbase * DDIM, 128, 16, STRB_A, DDIM, tid, 128);
    asm volatile("cp.async.commit_group;" ::: "memory");
    load_tile(sb + SB,            g_e_ext,             64, 18, STRB_B, KEXT, tid, 128);
    asm volatile("cp.async.commit_group;" ::: "memory");
    load_tile(sb + SB + SB_STAGE, g_e_ext + 64 * KEXT, 64, 18, STRB_B, KEXT, tid, 128);
    asm volatile("cp.async.commit_group;" ::: "memory");

    float m1[2][2], m2[2][2];
    int   k1[2][2];
    #pragma unroll
    for (int mf = 0; mf < 2; ++mf)
        #pragma unroll
        for (int h = 0; h < 2; ++h) {
            m1[mf][h] = -CUDART_INF_F; m2[mf][h] = -CUDART_INF_F; k1[mf][h] = 0;
        }

    const uint32_t a_off = (uint32_t)((wm * 32 + (lane & 15)) * STRB_A + (lane >> 4) * 16);
    const uint32_t b_off = (uint32_t)(((lane & 7) + ((lane >> 4) << 3)) * STRB_B
                                      + ((lane >> 3) & 1) * 16);

    // constant A fragment for the ext k-step: x_ext = [1, 0, ..., 0]
    uint32_t aext[4];
    aext[0] = aext[1] = (tig == 0) ? 0x00003C00u : 0u;
    aext[2] = aext[3] = 0u;

    asm volatile("cp.async.wait_group 2;" ::: "memory");
    __syncthreads();
    uint32_t aHr[8][2][4];
    #pragma unroll
    for (int ks = 0; ks < 8; ++ks)
        #pragma unroll
        for (int mf = 0; mf < 2; ++mf)
            ldsm4(aHr[ks][mf], sb + SA_HI + a_off + mf * 4352 + ks * 32);

    for (int it = 0; it < 16; ++it) {
        asm volatile("cp.async.wait_group 1;" ::: "memory");
        __syncthreads();
        const uint32_t bs = sb + SB + (uint32_t)(it & 1) * SB_STAGE;

        float acc[2][8][4];
        #pragma unroll
        for (int mf = 0; mf < 2; ++mf)
            #pragma unroll
            for (int nf = 0; nf < 8; ++nf)
                #pragma unroll
                for (int r = 0; r < 4; ++r) acc[mf][nf][r] = 0.0f;

        uint32_t bHb[2][4][4];
        #pragma unroll
        for (int p = 0; p < 4; ++p)
            ldsm4(bHb[0][p], bs + b_off + p * 4864);

        #pragma unroll
        for (int ks = 0; ks < 9; ++ks) {
            const int cur = ks & 1, nxt = cur ^ 1;
            if (ks < 8) {
                #pragma unroll
                for (int p = 0; p < 4; ++p)
                    ldsm4(bHb[nxt][p], bs + b_off + p * 4864 + (ks + 1) * 32);
            }
            #pragma unroll
            for (int mf = 0; mf < 2; ++mf) {
                const uint32_t* A = (ks < 8) ? aHr[ks][mf] : aext;
                #pragma unroll
                for (int p = 0; p < 4; ++p) {
                    mma16816(acc[mf][2 * p],     A, &bHb[cur][p][0]);
                    mma16816(acc[mf][2 * p + 1], A, &bHb[cur][p][2]);
                }
            }
        }

        // epilogue: branchless top-2 max of raw acc; k ascending per thread
        #pragma unroll
        for (int mf = 0; mf < 2; ++mf)
            #pragma unroll
            for (int nf = 0; nf < 8; ++nf) {
                const int kb = it * 64 + nf * 8 + 2 * tig;
                const float* a4 = acc[mf][nf];
                #pragma unroll
                for (int h = 0; h < 2; ++h)
                    #pragma unroll
                    for (int j = 0; j < 2; ++j) {
                        float v = a4[h * 2 + j];
                        bool gt = v > m1[mf][h];
                        m2[mf][h] = gt ? m1[mf][h] : fmaxf(m2[mf][h], v);
                        k1[mf][h] = gt ? (kb + j) : k1[mf][h];
                        m1[mf][h] = gt ? v : m1[mf][h];
                    }
            }

        __syncthreads();
        if (it + 2 < 16)
            load_tile(bs, g_e_ext + (size_t)(it + 2) * 64 * KEXT, 64, 18, STRB_B, KEXT, tid, 128);
        asm volatile("cp.async.commit_group;" ::: "memory");
    }

    // two-phase quad merge
    #pragma unroll
    for (int mf = 0; mf < 2; ++mf)
        #pragma unroll
        for (int h = 0; h < 2; ++h) {
            float v1 = m1[mf][h];
            int   kk = k1[mf][h];
            #pragma unroll
            for (int o = 1; o <= 2; o <<= 1) {
                float ov = __shfl_xor_sync(0xffffffffu, v1, o);
                int   ok = __shfl_xor_sync(0xffffffffu, kk, o);
                if (ov > v1 || (ov == v1 && ok < kk)) { v1 = ov; kk = ok; }
            }
            float cand = (k1[mf][h] == kk) ? m2[mf][h] : m1[mf][h];
            #pragma unroll
            for (int o = 1; o <= 2; o <<= 1)
                cand = fmaxf(cand, __shfl_xor_sync(0xffffffffu, cand, o));

            if (tig == 0) {
                int row = rbase + wm * 32 + mf * 16 + gID + h * 8;
                g_idx[row] = kk;
                out[NDTOT + 1 + row] = (float)kk;
                if (v1 - cand < QMARG) {
                    unsigned q = atomicAdd(&g_nref, 1u);
                    g_refrows[q] = row;
                }
            }
        }
}

// ---------------------------------------------------------------------------
// Pass 2 refine (v3): exact f32x2 distance (R3 pairing & rounding) for queued
// rows over ALL 1024 codes. 16 rows/group share double-buffered emb chunks.
// Thread = (row = t&15, code-lane = t>>4): within a warp e-loads hit only 2
// distinct addresses (broadcast) and x-loads are hoisted out of the code loop
// -> ~10x less smem traffic per group than R15 (the 66us refine bottleneck).
// Accumulation order per code byte-identical to R3. First-min preserved.
// ---------------------------------------------------------------------------
__global__ __launch_bounds__(256)
void vq_refine(const float* __restrict__ x,
               const float* __restrict__ emb,
               float* __restrict__ out)
{
    extern __shared__ __align__(16) char smem[];
    const uint32_t sb = smem_to_u32(smem);
    float* xs    = (float*)(smem + RXS);     // [16][132]
    float* esq_s = (float*)(smem + RESQ);
    float* candv = (float*)(smem + RCV);
    int*   candk = (int*)(smem + RCK);
    const int t  = threadIdx.x;
    const int r  = t & 15;    // row within group  (16 distinct per warp)
    const int cl = t >> 4;    // code-lane         (2 distinct per warp)
    const int n = (int)g_nref;

    for (int i = t; i < KCODE; i += 256) esq_s[i] = g_esq[i];

    for (int g = blockIdx.x; g * 16 < n; g += gridDim.x) {
        __syncthreads();   // smem reuse guard across groups
        // gather 16 x-rows (tail clamped to last valid entry; benign dupes)
        for (int c = t; c < 16 * 32; c += 256) {
            int rr = c >> 5, cc = c & 31;
            int e = g * 16 + rr;
            int rid = g_refrows[e < n ? e : n - 1];
            *(float4*)&xs[rr * 132 + cc * 4] =
                ((const float4*)(x + (size_t)rid * DDIM))[cc];
        }
        // prologue: stage chunk 0 and 1
        #pragma unroll
        for (int s = 0; s < 2; ++s) {
            for (int c = t; c < 64 * 32; c += 256) {
                int rr = c >> 5, cc = c & 31;
                cpasync16(sb + RES + s * RES_STG + (uint32_t)rr * 528 + cc * 16,
                          (const void*)(emb + (size_t)(s * 64 + rr) * DDIM + cc * 4));
            }
            asm volatile("cp.async.commit_group;" ::: "memory");
        }

        const int myrow = g * 16 + r;
        const float xsq = g_xsq[g_refrows[myrow < n ? myrow : n - 1]];

        float bv = CUDART_INF_F;
        int   bk = 0x7fffffff;
        for (int ch = 0; ch < 16; ++ch) {
            asm volatile("cp.async.wait_group 1;" ::: "memory");
            __syncthreads();
            const char* es = smem + RES + (ch & 1) * RES_STG;
            const ulonglong2* xr = (const ulonglong2*)(xs + r * 132);

            // 4 codes per thread, x hoisted: per c, 1 x-load + 4 e-loads
            unsigned long long acc[4] = {0ULL, 0ULL, 0ULL, 0ULL};
            #pragma unroll 4
            for (int c = 0; c < 32; ++c) {
                ulonglong2 xv = xr[c];
                #pragma unroll
                for (int jj = 0; jj < 4; ++jj) {
                    const ulonglong2 ev = *(const ulonglong2*)
                        (es + (cl + jj * 16) * 528 + c * 16);
                    fma2(acc[jj], xv.x, ev.x);
                    fma2(acc[jj], xv.y, ev.y);
                }
            }
            #pragma unroll
            for (int jj = 0; jj < 4; ++jj) {
                const int k = ch * 64 + cl + jj * 16;
                float2 p = *reinterpret_cast<float2*>(&acc[jj]);
                float dot = __fadd_rn(p.x, p.y);
                float d2 = __fadd_rn(__fsub_rn(xsq, 2.0f * dot), esq_s[k]);
                if (d2 < bv || (d2 == bv && k < bk)) { bv = d2; bk = k; }
            }

            __syncthreads();   // all done reading stage (ch&1)
            if (ch + 2 < 16) {
                for (int c = t; c < 64 * 32; c += 256) {
                    int rr = c >> 5, cc = c & 31;
                    cpasync16(sb + RES + (ch & 1) * RES_STG + (uint32_t)rr * 528 + cc * 16,
                              (const void*)(emb + (size_t)((ch + 2) * 64 + rr) * DDIM + cc * 4));
                }
            }
            asm volatile("cp.async.commit_group;" ::: "memory");
        }
        candv[r * 16 + cl] = bv;
        candk[r * 16 + cl] = bk;
        __syncthreads();
        if (t < 16) {
            float v = candv[t * 16];
            int   k = candk[t * 16];
            #pragma unroll
            for (int c = 1; c < 16; ++c) {
                float vo = candv[t * 16 + c];
                int   ko = candk[t * 16 + c];
                if (vo < v || (vo == v && ko < k)) { v = vo; k = ko; }
            }
            int e = g * 16 + t;
            if (e < n) {
                int rid = g_refrows[e];
                g_idx[rid] = k;
                out[NDTOT + 1 + rid] = (float)k;
            }
        }
    }
}

// ---------------------------------------------------------------------------
// quantized output (gather) + fp64 MSE, loss finalized by last block
// ---------------------------------------------------------------------------
__global__ __launch_bounds__(256)
void quant_kernel(const float* __restrict__ x,
                  const float* __restrict__ emb,
                  float* __restrict__ out)
{
    __shared__ double sred[256];
    __shared__ bool last;
    const int total4 = NDTOT / 4;  // 1048576
    double s = 0.0;
    for (int p = blockIdx.x * 256 + threadIdx.x; p < total4; p += gridDim.x * 256) {
        int row = p >> 5, d4 = p & 31;
        int k = g_idx[row];
        float4 q  = *(const float4*)&emb[(size_t)k * DDIM + d4 * 4];
        float4 xv = *(const float4*)&x[(size_t)p * 4];
        ((float4*)out)[p] = q;
        float a = q.x - xv.x, b = q.y - xv.y, c = q.z - xv.z, d = q.w - xv.w;
        s += (double)a * a + (double)b * b + (double)c * c + (double)d * d;
    }
    sred[threadIdx.x] = s;
    __syncthreads();
    for (int o = 128; o > 0; o >>= 1) {
        if (threadIdx.x < o) sred[threadIdx.x] += sred[threadIdx.x + o];
        __syncthreads();
    }
    if (threadIdx.x == 0) {
        g_part[blockIdx.x] = sred[0];
        __threadfence();
        unsigned v = atomicAdd(&g_done, 1u);
        last = (v == 1023u);
    }
    __syncthreads();
    if (last) {
        double tsum = 0.0;
        for (int i = threadIdx.x; i < 1024; i += 256) tsum += g_part[i];
        sred[threadIdx.x] = tsum;
        __syncthreads();
        for (int o = 128; o > 0; o >>= 1) {
            if (threadIdx.x < o) sred[threadIdx.x] += sred[threadIdx.x + o];
            __syncthreads();
        }
        if (threadIdx.x == 0) {
            out[NDTOT] = (float)(1.25 * (sred[0] / (double)NDTOT));
            g_done = 0;   // reset for next graph replay
        }
    }
}

// ---------------------------------------------------------------------------
extern "C" void kernel_launch(void* const* d_in, const int* in_sizes, int n_in,
                              void* d_out, int out_size)
{
    const float* x   = (const float*)d_in[0];
    const float* emb = (const float*)d_in[1];
    float* out = (float*)d_out;

    cudaFuncSetAttribute(vq_pass1,
                         cudaFuncAttributeMaxDynamicSharedMemorySize, SMEM_P1);
    cudaFuncSetAttribute(vq_refine,
                         cudaFuncAttributeMaxDynamicSharedMemorySize, SMEM_RF);

    esq_kernel<<<KCODE / 8, 256>>>(emb);                          // resets g_nref
    convert_emb_kernel<<<(KCODE * KEXT + 255) / 256, 256>>>(emb); // needs g_esq
    convert_x_kernel<<<N_ROWS / 64, 256>>>(x);
    vq_pass1<<<N_ROWS / 128, 128, SMEM_P1>>>(out);
    vq_refine<<<512, 256, SMEM_RF>>>(x, emb, out);
    quant_kernel<<<1024, 256>>>(x, emb, out);
}

// round 17
// speedup vs baseline: 1.4797x; 1.1834x over previous
#include <cuda_runtime.h>
#include <cuda_fp16.h>
#include <math_constants.h>
#include <cstdint>

// ---------------------------------------------------------------------------
// Problem constants
// ---------------------------------------------------------------------------
#define N_ROWS 32768
#define DDIM   128
#define KCODE  1024
#define NDTOT  (N_ROWS * DDIM)   // 4194304
#define KEXT   144               // 128 dims + 1 esq-fold dim + 15 zero pad
#define QMARG  0.024f            // acc units = d2 9.4e-5

// scratch (no cudaMalloc allowed)
__device__ __align__(16) __half g_x_hi[NDTOT];
__device__ __align__(16) __half g_e_ext[KCODE * KEXT];
__device__ float        g_xsq[N_ROWS];
__device__ float        g_esq[KCODE];
__device__ int          g_idx[N_ROWS];
__device__ int          g_refrows[N_ROWS];   // (iter-mask << 15) | row
__device__ unsigned int g_nref;
__device__ double       g_part[1024];
__device__ unsigned int g_done;

// ---------------------------------------------------------------------------
// helpers
// ---------------------------------------------------------------------------
__device__ __forceinline__ uint32_t smem_to_u32(const void* p) {
    uint32_t a;
    asm("{ .reg .u64 t; cvta.to.shared.u64 t, %1; cvt.u32.u64 %0, t; }"
        : "=r"(a) : "l"(p));
    return a;
}

__device__ __forceinline__ void ldsm4(uint32_t* r, uint32_t addr) {
    asm volatile("ldmatrix.sync.aligned.m8n8.x4.shared.b16 {%0,%1,%2,%3}, [%4];"
                 : "=r"(r[0]), "=r"(r[1]), "=r"(r[2]), "=r"(r[3]) : "r"(addr));
}

__device__ __forceinline__ void mma16816(float* d, const uint32_t* a,
                                         const uint32_t* b) {
    asm volatile(
        "mma.sync.aligned.m16n8k16.row.col.f32.f16.f16.f32 "
        "{%0,%1,%2,%3}, {%4,%5,%6,%7}, {%8,%9}, {%0,%1,%2,%3};"
        : "+f"(d[0]), "+f"(d[1]), "+f"(d[2]), "+f"(d[3])
        : "r"(a[0]), "r"(a[1]), "r"(a[2]), "r"(a[3]), "r"(b[0]), "r"(b[1]));
}

// packed fp32x2 FMA (R3-proven exact-dot building block)
__device__ __forceinline__ void fma2(unsigned long long& d,
                                     unsigned long long a,
                                     unsigned long long b) {
    asm("fma.rn.f32x2 %0, %1, %2, %0;" : "+l"(d) : "l"(a), "l"(b));
}

__device__ __forceinline__ void cpasync16(uint32_t dst, const void* src) {
    asm volatile("cp.async.cg.shared.global [%0], [%1], 16;"
                 :: "r"(dst), "l"(src) : "memory");
}

// cp.async a [rows x rowlen-half] tile into padded smem
__device__ __forceinline__ void load_tile(uint32_t dst,
                                          const __half* __restrict__ g,
                                          int rows, int chunks, int strb,
                                          int rowlen, int t, int nt) {
    for (int c = t; c < rows * chunks; c += nt) {
        int r = c / chunks, ch = c - r * chunks;
        cpasync16(dst + (uint32_t)r * strb + ch * 16,
                  (const void*)(g + (size_t)r * rowlen + ch * 8));
    }
}

// pass-1 smem layout (bytes)
#define STRB_A  272
#define STRB_B  304
#define SA_HI   0
#define SB      34816
#define SB_STAGE 19456
#define SITMAX  73728          // 128 rows x 17 floats (pad) = 8704
#define SMEM_P1 82432          // x2 CTAs = 164864 <= 227KB/SM

// ---------------------------------------------------------------------------
// e_sq + g_nref reset
// ---------------------------------------------------------------------------
__global__ void esq_kernel(const float* __restrict__ emb) {
    if (blockIdx.x == 0 && threadIdx.x == 0) g_nref = 0;
    int warp = (blockIdx.x * blockDim.x + threadIdx.x) >> 5;
    int lane = threadIdx.x & 31;
    if (warp < KCODE) {
        float4 v = *(const float4*)&emb[(size_t)warp * DDIM + lane * 4];
        float s = v.x * v.x + v.y * v.y + v.z * v.z + v.w * v.w;
        #pragma unroll
        for (int o = 16; o > 0; o >>= 1)
            s += __shfl_xor_sync(0xffffffffu, s, o);
        if (lane == 0) g_esq[warp] = s;
    }
}

// emb -> extended fp16: cols 0..127 = e*512, col 128 = -256*esq, 129..143 = 0
__global__ void convert_emb_kernel(const float* __restrict__ emb) {
    int i = blockIdx.x * blockDim.x + threadIdx.x;
    if (i < KCODE * KEXT) {
        int k = i / KEXT, col = i - k * KEXT;
        float v = 0.0f;
        if (col < DDIM)       v = emb[k * DDIM + col] * 512.0f;
        else if (col == DDIM) v = -256.0f * g_esq[k];
        g_e_ext[i] = __float2half_rn(v);
    }
}

// x -> fp16 + per-row x_sq (serial ascending-d, matches R3)
__global__ __launch_bounds__(256)
void convert_x_kernel(const float* __restrict__ x) {
    __shared__ float xs[64 * 132];
    const int rb = blockIdx.x * 64;
    const float4* xg = (const float4*)(x + (size_t)rb * DDIM);
    for (int t = threadIdx.x; t < 64 * 32; t += 256) {
        int r = t >> 5, c = t & 31;
        *(float4*)&xs[r * 132 + c * 4] = xg[r * 32 + c];
    }
    __syncthreads();
    if (threadIdx.x < 64) {
        const float* row = &xs[threadIdx.x * 132];
        float s = 0.0f;
        #pragma unroll 8
        for (int d = 0; d < DDIM; ++d)
            s = __fadd_rn(s, __fmul_rn(row[d], row[d]));
        g_xsq[rb + threadIdx.x] = s;
    }
    for (int i = threadIdx.x; i < 64 * DDIM; i += 256) {
        int r = i >> 7, c = i & 127;
        g_x_hi[(size_t)(rb + r) * DDIM + c] = __float2half_rn(xs[r * 132 + c]);
    }
}

// ---------------------------------------------------------------------------
// Pass 1: hi-only HMMA, esq folded into K-dim -> argmax(acc) == argmin(d2).
// Epilogue v2: per-iteration fmax tree (15 FMAX) + RARE argmax rescan when
// the iteration beats the running max (preserves first-k tie-break and true
// global top-2). Quad-max of each iteration stored to itmax[row][it]; queued
// rows carry a 16-bit mask of iterations within QMARG of v1 -> refine scans
// only those iterations' 64-code blocks.
// ---------------------------------------------------------------------------
__global__ __launch_bounds__(128, 2)
void vq_pass1(float* __restrict__ out)
{
    extern __shared__ __align__(16) char smem[];
    const uint32_t sb = smem_to_u32(smem);
    float* itmax = (float*)(smem + SITMAX);   // [128][17]
    const int tid  = threadIdx.x;
    const int lane = tid & 31;
    const int wm   = tid >> 5;
    const int gID  = lane >> 2;
    const int tig  = lane & 3;
    const int rbase = blockIdx.x * 128;

    // prologue: group0 = A; group1 = B stage0; group2 = B stage1
    load_tile(sb + SA_HI, g_x_hi + (size_t)rbase * DDIM, 128, 16, STRB_A, DDIM, tid, 128);
    asm volatile("cp.async.commit_group;" ::: "memory");
    load_tile(sb + SB,            g_e_ext,             64, 18, STRB_B, KEXT, tid, 128);
    asm volatile("cp.async.commit_group;" ::: "memory");
    load_tile(sb + SB + SB_STAGE, g_e_ext + 64 * KEXT, 64, 18, STRB_B, KEXT, tid, 128);
    asm volatile("cp.async.commit_group;" ::: "memory");

    float m1[2][2], m2[2][2];
    int   k1[2][2];
    #pragma unroll
    for (int mf = 0; mf < 2; ++mf)
        #pragma unroll
        for (int h = 0; h < 2; ++h) {
            m1[mf][h] = -CUDART_INF_F; m2[mf][h] = -CUDART_INF_F; k1[mf][h] = 0;
        }

    const uint32_t a_off = (uint32_t)((wm * 32 + (lane & 15)) * STRB_A + (lane >> 4) * 16);
    const uint32_t b_off = (uint32_t)(((lane & 7) + ((lane >> 4) << 3)) * STRB_B
                                      + ((lane >> 3) & 1) * 16);

    // constant A fragment for the ext k-step: x_ext = [1, 0, ..., 0]
    uint32_t aext[4];
    aext[0] = aext[1] = (tig == 0) ? 0x00003C00u : 0u;
    aext[2] = aext[3] = 0u;

    asm volatile("cp.async.wait_group 2;" ::: "memory");
    __syncthreads();
    uint32_t aHr[8][2][4];
    #pragma unroll
    for (int ks = 0; ks < 8; ++ks)
        #pragma unroll
        for (int mf = 0; mf < 2; ++mf)
            ldsm4(aHr[ks][mf], sb + SA_HI + a_off + mf * 4352 + ks * 32);

    for (int it = 0; it < 16; ++it) {
        asm volatile("cp.async.wait_group 1;" ::: "memory");
        __syncthreads();
        const uint32_t bs = sb + SB + (uint32_t)(it & 1) * SB_STAGE;

        float acc[2][8][4];
        #pragma unroll
        for (int mf = 0; mf < 2; ++mf)
            #pragma unroll
            for (int nf = 0; nf < 8; ++nf)
                #pragma unroll
                for (int r = 0; r < 4; ++r) acc[mf][nf][r] = 0.0f;

        uint32_t bHb[2][4][4];
        #pragma unroll
        for (int p = 0; p < 4; ++p)
            ldsm4(bHb[0][p], bs + b_off + p * 4864);

        #pragma unroll
        for (int ks = 0; ks < 9; ++ks) {
            const int cur = ks & 1, nxt = cur ^ 1;
            if (ks < 8) {
                #pragma unroll
                for (int p = 0; p < 4; ++p)
                    ldsm4(bHb[nxt][p], bs + b_off + p * 4864 + (ks + 1) * 32);
            }
            #pragma unroll
            for (int mf = 0; mf < 2; ++mf) {
                const uint32_t* A = (ks < 8) ? aHr[ks][mf] : aext;
                #pragma unroll
                for (int p = 0; p < 4; ++p) {
                    mma16816(acc[mf][2 * p],     A, &bHb[cur][p][0]);
                    mma16816(acc[mf][2 * p + 1], A, &bHb[cur][p][2]);
                }
            }
        }

        // epilogue: fmax tree per (row-slot, iteration); rare rescan on new max
        #pragma unroll
        for (int mf = 0; mf < 2; ++mf)
            #pragma unroll
            for (int h = 0; h < 2; ++h) {
                float lmax = -CUDART_INF_F;
                #pragma unroll
                for (int nf = 0; nf < 8; ++nf) {
                    lmax = fmaxf(lmax, acc[mf][nf][h * 2]);
                    lmax = fmaxf(lmax, acc[mf][nf][h * 2 + 1]);
                }
                if (lmax > m1[mf][h]) {
                    // rescan: first-k argmax + iteration second-best
                    float second = -CUDART_INF_F;
                    int karg = -1;
                    #pragma unroll
                    for (int nf = 0; nf < 8; ++nf)
                        #pragma unroll
                        for (int j = 0; j < 2; ++j) {
                            float v = acc[mf][nf][h * 2 + j];
                            if (v == lmax && karg < 0)
                                karg = it * 64 + nf * 8 + 2 * tig + j;
                            else
                                second = fmaxf(second, v);
                        }
                    m2[mf][h] = fmaxf(m1[mf][h], second);
                    m1[mf][h] = lmax;
                    k1[mf][h] = karg;
                } else {
                    m2[mf][h] = fmaxf(m2[mf][h], lmax);
                }
                // iteration max over the whole 64-code block (quad reduce)
                float im = fmaxf(lmax, __shfl_xor_sync(0xffffffffu, lmax, 1));
                im = fmaxf(im, __shfl_xor_sync(0xffffffffu, im, 2));
                if (tig == 0) {
                    int rloc = wm * 32 + mf * 16 + gID + h * 8;
                    itmax[rloc * 17 + it] = im;
                }
            }

        __syncthreads();
        if (it + 2 < 16)
            load_tile(bs, g_e_ext + (size_t)(it + 2) * 64 * KEXT, 64, 18, STRB_B, KEXT, tid, 128);
        asm volatile("cp.async.commit_group;" ::: "memory");
    }

    // two-phase quad merge
    #pragma unroll
    for (int mf = 0; mf < 2; ++mf)
        #pragma unroll
        for (int h = 0; h < 2; ++h) {
            float v1 = m1[mf][h];
            int   kk = k1[mf][h];
            #pragma unroll
            for (int o = 1; o <= 2; o <<= 1) {
                float ov = __shfl_xor_sync(0xffffffffu, v1, o);
                int   ok = __shfl_xor_sync(0xffffffffu, kk, o);
                if (ov > v1 || (ov == v1 && ok < kk)) { v1 = ov; kk = ok; }
            }
            float cand = (k1[mf][h] == kk) ? m2[mf][h] : m1[mf][h];
            #pragma unroll
            for (int o = 1; o <= 2; o <<= 1)
                cand = fmaxf(cand, __shfl_xor_sync(0xffffffffu, cand, o));

            if (tig == 0) {
                int rloc = wm * 32 + mf * 16 + gID + h * 8;
                int row = rbase + rloc;
                g_idx[row] = kk;
                out[NDTOT + 1 + row] = (float)kk;
                if (v1 - cand < QMARG) {
                    unsigned msk = 0;
                    #pragma unroll
                    for (int b = 0; b < 16; ++b)
                        if (itmax[rloc * 17 + b] > v1 - QMARG) msk |= 1u << b;
                    unsigned q = atomicAdd(&g_nref, 1u);
                    g_refrows[q] = (int)((msk << 15) | (unsigned)row);
                }
            }
        }
}

// ---------------------------------------------------------------------------
// Pass 2 refine (v5, shortlist): per queued row evaluate ONLY the masked
// iterations' 64-code blocks with the exact R3 f32x2 pipeline (identical
// pairing, rounding, first-min via lex (v,k)). One code per thread, x row
// broadcast from smem, e rows from (hot) L2. Every code that can exactly win
// or tie lies in a masked iteration (others are > QMARG below v1).
// ---------------------------------------------------------------------------
__global__ __launch_bounds__(128)
void vq_refine(const float* __restrict__ x,
               const float* __restrict__ emb,
               float* __restrict__ out)
{
    __shared__ __align__(16) float xrow[DDIM];
    __shared__ float rv[128];
    __shared__ int   rk[128];
    const int t = threadIdx.x;
    const int n = (int)g_nref;

    for (int e = blockIdx.x; e < n; e += gridDim.x) {
        const unsigned pk = (unsigned)g_refrows[e];
        const int row = (int)(pk & 0x7FFFu);
        const unsigned msk = pk >> 15;
        __syncthreads();   // protect xrow/rv/rk reuse across entries
        if (t < 32)
            ((float4*)xrow)[t] = ((const float4*)(x + (size_t)row * DDIM))[t];
        __syncthreads();
        const float xsq = g_xsq[row];

        float bv = CUDART_INF_F;
        int   bk = 0x7fffffff;
        const int half = t >> 6;    // masked iterations alternate halves
        const int cl   = t & 63;
        int idx = 0;
        for (int b = 0; b < 16; ++b) {
            if (!(msk & (1u << b))) continue;
            if ((idx & 1) == half) {
                const int k = b * 64 + cl;
                const ulonglong2* er = (const ulonglong2*)(emb + (size_t)k * DDIM);
                const ulonglong2* xr = (const ulonglong2*)xrow;
                unsigned long long acc = 0ULL;
                #pragma unroll 4
                for (int c = 0; c < 32; ++c) {
                    ulonglong2 xv = xr[c];
                    ulonglong2 ev = er[c];
                    fma2(acc, xv.x, ev.x);
                    fma2(acc, xv.y, ev.y);
                }
                float2 p = *reinterpret_cast<float2*>(&acc);
                float dot = __fadd_rn(p.x, p.y);
                float d2 = __fadd_rn(__fsub_rn(xsq, 2.0f * dot), g_esq[k]);
                if (d2 < bv || (d2 == bv && k < bk)) { bv = d2; bk = k; }
            }
            idx++;
        }
        rv[t] = bv; rk[t] = bk;
        __syncthreads();
        for (int o = 64; o > 0; o >>= 1) {
            if (t < o) {
                float vo = rv[t + o]; int ko = rk[t + o];
                if (vo < rv[t] || (vo == rv[t] && ko < rk[t])) {
                    rv[t] = vo; rk[t] = ko;
                }
            }
            __syncthreads();
        }
        if (t == 0) {
            g_idx[row] = rk[0];
            out[NDTOT + 1 + row] = (float)rk[0];
        }
    }
}

// ---------------------------------------------------------------------------
// quantized output (gather) + fp64 MSE, loss finalized by last block
// ---------------------------------------------------------------------------
__global__ __launch_bounds__(256)
void quant_kernel(const float* __restrict__ x,
                  const float* __restrict__ emb,
                  float* __restrict__ out)
{
    __shared__ double sred[256];
    __shared__ bool last;
    const int total4 = NDTOT / 4;  // 1048576
    double s = 0.0;
    for (int p = blockIdx.x * 256 + threadIdx.x; p < total4; p += gridDim.x * 256) {
        int row = p >> 5, d4 = p & 31;
        int k = g_idx[row];
        float4 q  = *(const float4*)&emb[(size_t)k * DDIM + d4 * 4];
        float4 xv = *(const float4*)&x[(size_t)p * 4];
        ((float4*)out)[p] = q;
        float a = q.x - xv.x, b = q.y - xv.y, c = q.z - xv.z, d = q.w - xv.w;
        s += (double)a * a + (double)b * b + (double)c * c + (double)d * d;
    }
    sred[threadIdx.x] = s;
    __syncthreads();
    for (int o = 128; o > 0; o >>= 1) {
        if (threadIdx.x < o) sred[threadIdx.x] += sred[threadIdx.x + o];
        __syncthreads();
    }
    if (threadIdx.x == 0) {
        g_part[blockIdx.x] = sred[0];
        __threadfence();
        unsigned v = atomicAdd(&g_done, 1u);
        last = (v == 1023u);
    }
    __syncthreads();
    if (last) {
        double tsum = 0.0;
        for (int i = threadIdx.x; i < 1024; i += 256) tsum += g_part[i];
        sred[threadIdx.x] = tsum;
        __syncthreads();
        for (int o = 128; o > 0; o >>= 1) {
            if (threadIdx.x < o) sred[threadIdx.x] += sred[threadIdx.x + o];
            __syncthreads();
        }
        if (threadIdx.x == 0) {
            out[NDTOT] = (float)(1.25 * (sred[0] / (double)NDTOT));
            g_done = 0;   // reset for next graph replay
        }
    }
}

// ---------------------------------------------------------------------------
extern "C" void kernel_launch(void* const* d_in, const int* in_sizes, int n_in,
                              void* d_out, int out_size)
{
    const float* x   = (const float*)d_in[0];
    const float* emb = (const float*)d_in[1];
    float* out = (float*)d_out;

    cudaFuncSetAttribute(vq_pass1,
                         cudaFuncAttributeMaxDynamicSharedMemorySize, SMEM_P1);

    esq_kernel<<<KCODE / 8, 256>>>(emb);                          // resets g_nref
    convert_emb_kernel<<<(KCODE * KEXT + 255) / 256, 256>>>(emb); // needs g_esq
    convert_x_kernel<<<N_ROWS / 64, 256>>>(x);
    vq_pass1<<<N_ROWS / 128, 128, SMEM_P1>>>(out);
    vq_refine<<<2048, 128>>>(x, emb, out);
    quant_kernel<<<1024, 256>>>(x, emb, out);
}